// round 1
// baseline (speedup 1.0000x reference)
#include <cuda_runtime.h>
#include <cuda_bf16.h>

// roi_feature: dual bilinear grid_sample with a shared 16x16 grid per batch.
// inputs: [0] original_features f32 (32,256,64,64)
//         [1] lab f32 (32,1,5)
//         [2] attack_features f32 (32,256,64,64)
// output: concat(out1, out2), each (32,256,16,16) f32.

#define B_   32
#define C_   256
#define H_   64
#define W_   64
#define BIN_ 16
#define CH_PER_BLK 8

__global__ __launch_bounds__(256, 8)
void roi_feature_kernel(const float* __restrict__ orig,
                        const float* __restrict__ lab,
                        const float* __restrict__ att,
                        float* __restrict__ out)
{
    const int b      = blockIdx.x;           // 0..31
    const int cchunk = blockIdx.y;           // 0..31, 8 channels each
    const int t      = threadIdx.x;          // 0..255
    const int i      = t >> 4;               // bin row  (drives y)
    const int j      = t & 15;               // bin col  (drives x)

    const float* L = lab + b * 5;
    const float l1 = __ldg(L + 1);
    const float l2 = __ldg(L + 2);
    const float l3 = __ldg(L + 3);
    const float l4 = __ldg(L + 4);

    // grid[...,0] = mesh_y[b, j] -> x pixel; grid[...,1] = mesh_x[b, i] -> y pixel
    const float gx = 2.0f * (float)(j - BIN_ / 2) * l3 / (float)BIN_ + (l1 * 2.0f - 1.0f);
    const float gy = 2.0f * (float)(i - BIN_ / 2) * l4 / (float)BIN_ + (l2 * 2.0f - 1.0f);

    const float x = ((gx + 1.0f) * (float)W_ - 1.0f) * 0.5f;
    const float y = ((gy + 1.0f) * (float)H_ - 1.0f) * 0.5f;

    const float x0f = floorf(x);
    const float y0f = floorf(y);
    const int x0 = (int)x0f;
    const int y0 = (int)y0f;
    const int x1 = x0 + 1;
    const int y1 = y0 + 1;

    const float wx1 = x - x0f, wx0 = 1.0f - wx1;
    const float wy1 = y - y0f, wy0 = 1.0f - wy1;

    const float vx0 = (x0 >= 0 && x0 < W_) ? 1.0f : 0.0f;
    const float vx1 = (x1 >= 0 && x1 < W_) ? 1.0f : 0.0f;
    const float vy0 = (y0 >= 0 && y0 < H_) ? 1.0f : 0.0f;
    const float vy1 = (y1 >= 0 && y1 < H_) ? 1.0f : 0.0f;

    const float w00 = wx0 * wy0 * vx0 * vy0;
    const float w01 = wx1 * wy0 * vx1 * vy0;
    const float w10 = wx0 * wy1 * vx0 * vy1;
    const float w11 = wx1 * wy1 * vx1 * vy1;

    const int xc0 = min(max(x0, 0), W_ - 1);
    const int xc1 = min(max(x1, 0), W_ - 1);
    const int yc0 = min(max(y0, 0), H_ - 1);
    const int yc1 = min(max(y1, 0), H_ - 1);

    const int o00 = yc0 * W_ + xc0;
    const int o01 = yc0 * W_ + xc1;
    const int o10 = yc1 * W_ + xc0;
    const int o11 = yc1 * W_ + xc1;

    const size_t plane   = (size_t)H_ * W_;                     // 4096
    const size_t base    = ((size_t)b * C_ + (size_t)cchunk * CH_PER_BLK) * plane;
    const size_t outbase = ((size_t)b * C_ + (size_t)cchunk * CH_PER_BLK) * (BIN_ * BIN_) + t;
    const size_t out2off = (size_t)B_ * C_ * BIN_ * BIN_;       // 2,097,152

    #pragma unroll
    for (int cc = 0; cc < CH_PER_BLK; ++cc) {
        const float* p = orig + base + (size_t)cc * plane;
        const float* q = att  + base + (size_t)cc * plane;

        const float p00 = __ldg(p + o00);
        const float p01 = __ldg(p + o01);
        const float p10 = __ldg(p + o10);
        const float p11 = __ldg(p + o11);
        const float q00 = __ldg(q + o00);
        const float q01 = __ldg(q + o01);
        const float q10 = __ldg(q + o10);
        const float q11 = __ldg(q + o11);

        const float r1 = p00 * w00 + p01 * w01 + p10 * w10 + p11 * w11;
        const float r2 = q00 * w00 + q01 * w01 + q10 * w10 + q11 * w11;

        out[outbase + (size_t)cc * (BIN_ * BIN_)]           = r1;
        out[out2off + outbase + (size_t)cc * (BIN_ * BIN_)] = r2;
    }
}

extern "C" void kernel_launch(void* const* d_in, const int* in_sizes, int n_in,
                              void* d_out, int out_size)
{
    const float* orig = (const float*)d_in[0];
    const float* lab  = (const float*)d_in[1];
    const float* att  = (const float*)d_in[2];
    float* out        = (float*)d_out;

    dim3 grid(B_, C_ / CH_PER_BLK);   // (32, 32)
    roi_feature_kernel<<<grid, 256>>>(orig, lab, att, out);
}

// round 2
// speedup vs baseline: 1.1604x; 1.1604x over previous
#include <cuda_runtime.h>
#include <cuda_bf16.h>

// roi_feature: dual bilinear grid_sample with a shared 16x16 grid per batch.
// inputs: [0] original_features f32 (32,256,64,64)
//         [1] lab f32 (32,1,5)
//         [2] attack_features f32 (32,256,64,64)
// output: concat(out1, out2), each (32,256,16,16) f32.
//
// R2 strategy: latency-bound fix. Front-batch all 32 gather loads per thread
// (4 channels x 4 corners x 2 tensors) before any compute, CH_PER_BLK=4 for
// 2048 blocks (better wave balance), launch_bounds(256,4) to give ptxas
// register room for the load batch.

#define B_   32
#define C_   256
#define H_   64
#define W_   64
#define BIN_ 16
#define CH_PER_BLK 4

__global__ __launch_bounds__(256, 4)
void roi_feature_kernel(const float* __restrict__ orig,
                        const float* __restrict__ lab,
                        const float* __restrict__ att,
                        float* __restrict__ out)
{
    const int b      = blockIdx.x;           // 0..31
    const int cchunk = blockIdx.y;           // 0..63, 4 channels each
    const int t      = threadIdx.x;          // 0..255
    const int i      = t >> 4;               // bin row  (drives y)
    const int j      = t & 15;               // bin col  (drives x)

    const float* L = lab + b * 5;
    const float l1 = __ldg(L + 1);
    const float l2 = __ldg(L + 2);
    const float l3 = __ldg(L + 3);
    const float l4 = __ldg(L + 4);

    // grid[...,0] = mesh_y[b, j] -> x pixel; grid[...,1] = mesh_x[b, i] -> y pixel
    const float gx = 2.0f * (float)(j - BIN_ / 2) * l3 / (float)BIN_ + (l1 * 2.0f - 1.0f);
    const float gy = 2.0f * (float)(i - BIN_ / 2) * l4 / (float)BIN_ + (l2 * 2.0f - 1.0f);

    const float x = ((gx + 1.0f) * (float)W_ - 1.0f) * 0.5f;
    const float y = ((gy + 1.0f) * (float)H_ - 1.0f) * 0.5f;

    const float x0f = floorf(x);
    const float y0f = floorf(y);
    const int x0 = (int)x0f;
    const int y0 = (int)y0f;
    const int x1 = x0 + 1;
    const int y1 = y0 + 1;

    const float wx1 = x - x0f, wx0 = 1.0f - wx1;
    const float wy1 = y - y0f, wy0 = 1.0f - wy1;

    const float vx0 = (x0 >= 0 && x0 < W_) ? 1.0f : 0.0f;
    const float vx1 = (x1 >= 0 && x1 < W_) ? 1.0f : 0.0f;
    const float vy0 = (y0 >= 0 && y0 < H_) ? 1.0f : 0.0f;
    const float vy1 = (y1 >= 0 && y1 < H_) ? 1.0f : 0.0f;

    const float w00 = wx0 * wy0 * vx0 * vy0;
    const float w01 = wx1 * wy0 * vx1 * vy0;
    const float w10 = wx0 * wy1 * vx0 * vy1;
    const float w11 = wx1 * wy1 * vx1 * vy1;

    const int xc0 = min(max(x0, 0), W_ - 1);
    const int xc1 = min(max(x1, 0), W_ - 1);
    const int yc0 = min(max(y0, 0), H_ - 1);
    const int yc1 = min(max(y1, 0), H_ - 1);

    const int o00 = yc0 * W_ + xc0;
    const int o01 = yc0 * W_ + xc1;
    const int o10 = yc1 * W_ + xc0;
    const int o11 = yc1 * W_ + xc1;

    const size_t plane   = (size_t)H_ * W_;                     // 4096
    const size_t base    = ((size_t)b * C_ + (size_t)cchunk * CH_PER_BLK) * plane;
    const size_t outbase = ((size_t)b * C_ + (size_t)cchunk * CH_PER_BLK) * (BIN_ * BIN_) + t;
    const size_t out2off = (size_t)B_ * C_ * BIN_ * BIN_;       // 2,097,152

    // ---- Phase 1: issue ALL gather loads (32 in flight per thread) ----
    float p[CH_PER_BLK][4];
    float q[CH_PER_BLK][4];

    #pragma unroll
    for (int cc = 0; cc < CH_PER_BLK; ++cc) {
        const float* pp = orig + base + (size_t)cc * plane;
        p[cc][0] = __ldg(pp + o00);
        p[cc][1] = __ldg(pp + o01);
        p[cc][2] = __ldg(pp + o10);
        p[cc][3] = __ldg(pp + o11);
    }
    #pragma unroll
    for (int cc = 0; cc < CH_PER_BLK; ++cc) {
        const float* qq = att + base + (size_t)cc * plane;
        q[cc][0] = __ldg(qq + o00);
        q[cc][1] = __ldg(qq + o01);
        q[cc][2] = __ldg(qq + o10);
        q[cc][3] = __ldg(qq + o11);
    }

    // ---- Phase 2: compute + store ----
    #pragma unroll
    for (int cc = 0; cc < CH_PER_BLK; ++cc) {
        const float r1 = p[cc][0] * w00 + p[cc][1] * w01 + p[cc][2] * w10 + p[cc][3] * w11;
        const float r2 = q[cc][0] * w00 + q[cc][1] * w01 + q[cc][2] * w10 + q[cc][3] * w11;
        out[outbase + (size_t)cc * (BIN_ * BIN_)]           = r1;
        out[out2off + outbase + (size_t)cc * (BIN_ * BIN_)] = r2;
    }
}

extern "C" void kernel_launch(void* const* d_in, const int* in_sizes, int n_in,
                              void* d_out, int out_size)
{
    const float* orig = (const float*)d_in[0];
    const float* lab  = (const float*)d_in[1];
    const float* att  = (const float*)d_in[2];
    float* out        = (float*)d_out;

    dim3 grid(B_, C_ / CH_PER_BLK);   // (32, 64)
    roi_feature_kernel<<<grid, 256>>>(orig, lab, att, out);
}